// round 14
// baseline (speedup 1.0000x reference)
#include <cuda_runtime.h>
#include <cstdint>

// out = relu( row_mask ? (features + residuals[0] + residuals[1]) : 0 )
// features:  (256, 128, 1024) f32
// residuals: (2, 256, 128, 1024) f32
// mol_slice: (256, 2) int64 OR int32 (runtime-detected)
//
// FINAL (best of 8 measured structural variants; identical-source re-benches
// span 46.2-50.1us kernel => machine noise; best profile: 79.4% DRAM,
// 6.29 TB/s on ~291MB actual traffic = practical DRAM-scheduler roofline):
//   - 4 consecutive rows per block (same batch: 4 | 128), 128 threads
//   - one 8-float (256-bit) slot per thread (Blackwell v8 global ld/st)
//   - ALL 12 v8 loads front-batched (384B in flight/thread) before compute
//   - masked rows: streaming zero store only, no loads (skips ~40% of traffic)
//   - linear CTA order (swizzle -1.6us, persistent grid -3.4us,
//     store/load pipelining -1.5us: all measured slower)

#define BATCH 256
#define MAX_ATOM 128
#define N_FEAT 1024
#define THREADS 128        // N_FEAT / 8
#define ROWS_PER_BLK 4

struct f8 { float v[8]; };

__device__ __forceinline__ f8 ldnc8(const float* p) {
    f8 r;
    asm volatile("ld.global.nc.v8.f32 {%0,%1,%2,%3,%4,%5,%6,%7}, [%8];"
                 : "=f"(r.v[0]), "=f"(r.v[1]), "=f"(r.v[2]), "=f"(r.v[3]),
                   "=f"(r.v[4]), "=f"(r.v[5]), "=f"(r.v[6]), "=f"(r.v[7])
                 : "l"(p));
    return r;
}

__device__ __forceinline__ void stcs8(float* p, const f8& r) {
    asm volatile("st.global.cs.v8.f32 [%0], {%1,%2,%3,%4,%5,%6,%7,%8};"
                 :: "l"(p),
                    "f"(r.v[0]), "f"(r.v[1]), "f"(r.v[2]), "f"(r.v[3]),
                    "f"(r.v[4]), "f"(r.v[5]), "f"(r.v[6]), "f"(r.v[7])
                 : "memory");
}

__global__ __launch_bounds__(THREADS)
void dense_block_end_kernel(const float* __restrict__ features,
                            const float* __restrict__ residuals,
                            const void*  __restrict__ mol_slice,
                            float* __restrict__ out)
{
    const int row0 = blockIdx.x * ROWS_PER_BLK;
    const int b    = row0 >> 7;                  // / MAX_ATOM
    const int a0   = row0 & (MAX_ATOM - 1);

    // mol_slice dtype sniff:
    //   int32: [M0, 1024, M1, 1024, ...] -> word[1] == 1024
    //   int64: [M0, 0, 1024, 0, ...]     -> word[1] == 0 (hi word, M <= 128)
    const int* ms32 = (const int*)mol_slice;
    int n_atoms;
    if (ms32[1] == N_FEAT) {
        n_atoms = ms32[2 * b];
    } else {
        n_atoms = (int)((const long long*)mol_slice)[2 * b];
    }

    const size_t res_stride = (size_t)BATCH * MAX_ATOM * N_FEAT;
    const size_t base0 = (size_t)row0 * N_FEAT + threadIdx.x * 8;

    // Front-batch ALL loads (up to 12 independent 256-bit LDGs), then compute.
    f8 f[ROWS_PER_BLK], r0[ROWS_PER_BLK], r1[ROWS_PER_BLK];
    bool act[ROWS_PER_BLK];

    #pragma unroll
    for (int i = 0; i < ROWS_PER_BLK; i++) {
        act[i] = (a0 + i) < n_atoms;
        const size_t base = base0 + (size_t)i * N_FEAT;
        if (act[i]) {
            f[i]  = ldnc8(features + base);
            r0[i] = ldnc8(residuals + base);
            r1[i] = ldnc8(residuals + res_stride + base);
        }
    }

    #pragma unroll
    for (int i = 0; i < ROWS_PER_BLK; i++) {
        const size_t base = base0 + (size_t)i * N_FEAT;
        f8 v;
        #pragma unroll
        for (int j = 0; j < 8; j++) v.v[j] = 0.f;
        if (act[i]) {
            #pragma unroll
            for (int j = 0; j < 8; j++)
                v.v[j] = fmaxf(f[i].v[j] + r0[i].v[j] + r1[i].v[j], 0.f);
        }
        stcs8(out + base, v);
    }
}

extern "C" void kernel_launch(void* const* d_in, const int* in_sizes, int n_in,
                              void* d_out, int out_size)
{
    const float* features  = (const float*)d_in[0];
    const float* residuals = (const float*)d_in[1];
    const void*  mol_slice = d_in[2];
    float* out = (float*)d_out;

    dense_block_end_kernel<<<(BATCH * MAX_ATOM) / ROWS_PER_BLK, THREADS>>>(
        features, residuals, mol_slice, out);
}

// round 15
// speedup vs baseline: 1.0429x; 1.0429x over previous
#include <cuda_runtime.h>
#include <cstdint>

// out = relu( row_mask ? (features + residuals[0] + residuals[1]) : 0 )
// features:  (256, 128, 1024) f32
// residuals: (2, 256, 128, 1024) f32
// mol_slice: (256, 2) int64 OR int32 (runtime-detected)
//
// FINAL (best of 8 measured structural variants; 5 identical-source benches
// span 46.2-50.5us kernel, bimodal with machine clock state; best profile:
// 79.4% DRAM, 6.29 TB/s on ~291MB actual traffic = practical roofline):
//   - 4 consecutive rows per block (same batch: 4 | 128), 128 threads
//   - one 8-float (256-bit) slot per thread (Blackwell v8 global ld/st)
//   - ALL 12 v8 loads front-batched (384B in flight/thread) before compute
//   - masked rows: streaming zero store only, no loads (skips ~40% of traffic)
//   - linear CTA order (swizzle -1.6us, persistent grid -3.4us,
//     store/load pipelining -1.5us: all measured slower)

#define BATCH 256
#define MAX_ATOM 128
#define N_FEAT 1024
#define THREADS 128        // N_FEAT / 8
#define ROWS_PER_BLK 4

struct f8 { float v[8]; };

__device__ __forceinline__ f8 ldnc8(const float* p) {
    f8 r;
    asm volatile("ld.global.nc.v8.f32 {%0,%1,%2,%3,%4,%5,%6,%7}, [%8];"
                 : "=f"(r.v[0]), "=f"(r.v[1]), "=f"(r.v[2]), "=f"(r.v[3]),
                   "=f"(r.v[4]), "=f"(r.v[5]), "=f"(r.v[6]), "=f"(r.v[7])
                 : "l"(p));
    return r;
}

__device__ __forceinline__ void stcs8(float* p, const f8& r) {
    asm volatile("st.global.cs.v8.f32 [%0], {%1,%2,%3,%4,%5,%6,%7,%8};"
                 :: "l"(p),
                    "f"(r.v[0]), "f"(r.v[1]), "f"(r.v[2]), "f"(r.v[3]),
                    "f"(r.v[4]), "f"(r.v[5]), "f"(r.v[6]), "f"(r.v[7])
                 : "memory");
}

__global__ __launch_bounds__(THREADS)
void dense_block_end_kernel(const float* __restrict__ features,
                            const float* __restrict__ residuals,
                            const void*  __restrict__ mol_slice,
                            float* __restrict__ out)
{
    const int row0 = blockIdx.x * ROWS_PER_BLK;
    const int b    = row0 >> 7;                  // / MAX_ATOM
    const int a0   = row0 & (MAX_ATOM - 1);

    // mol_slice dtype sniff:
    //   int32: [M0, 1024, M1, 1024, ...] -> word[1] == 1024
    //   int64: [M0, 0, 1024, 0, ...]     -> word[1] == 0 (hi word, M <= 128)
    const int* ms32 = (const int*)mol_slice;
    int n_atoms;
    if (ms32[1] == N_FEAT) {
        n_atoms = ms32[2 * b];
    } else {
        n_atoms = (int)((const long long*)mol_slice)[2 * b];
    }

    const size_t res_stride = (size_t)BATCH * MAX_ATOM * N_FEAT;
    const size_t base0 = (size_t)row0 * N_FEAT + threadIdx.x * 8;

    // Front-batch ALL loads (up to 12 independent 256-bit LDGs), then compute.
    f8 f[ROWS_PER_BLK], r0[ROWS_PER_BLK], r1[ROWS_PER_BLK];
    bool act[ROWS_PER_BLK];

    #pragma unroll
    for (int i = 0; i < ROWS_PER_BLK; i++) {
        act[i] = (a0 + i) < n_atoms;
        const size_t base = base0 + (size_t)i * N_FEAT;
        if (act[i]) {
            f[i]  = ldnc8(features + base);
            r0[i] = ldnc8(residuals + base);
            r1[i] = ldnc8(residuals + res_stride + base);
        }
    }

    #pragma unroll
    for (int i = 0; i < ROWS_PER_BLK; i++) {
        const size_t base = base0 + (size_t)i * N_FEAT;
        f8 v;
        #pragma unroll
        for (int j = 0; j < 8; j++) v.v[j] = 0.f;
        if (act[i]) {
            #pragma unroll
            for (int j = 0; j < 8; j++)
                v.v[j] = fmaxf(f[i].v[j] + r0[i].v[j] + r1[i].v[j], 0.f);
        }
        stcs8(out + base, v);
    }
}

extern "C" void kernel_launch(void* const* d_in, const int* in_sizes, int n_in,
                              void* d_out, int out_size)
{
    const float* features  = (const float*)d_in[0];
    const float* residuals = (const float*)d_in[1];
    const void*  mol_slice = d_in[2];
    float* out = (float*)d_out;

    dense_block_end_kernel<<<(BATCH * MAX_ATOM) / ROWS_PER_BLK, THREADS>>>(
        features, residuals, mol_slice, out);
}

// round 16
// speedup vs baseline: 1.0435x; 1.0006x over previous
#include <cuda_runtime.h>
#include <cstdint>

// out = relu( row_mask ? (features + residuals[0] + residuals[1]) : 0 )
// features:  (256, 128, 1024) f32
// residuals: (2, 256, 128, 1024) f32
// mol_slice: (256, 2) int64 OR int32 (runtime-detected)
//
// FINAL (best of 8 measured structural variants; 6 identical-source benches
// span 46.2-50.5us kernel / 53.76-56.06us dur, bimodal with machine clock
// state; best profile: 79.4% DRAM, 6.29 TB/s on ~291MB actual traffic =
// practical DRAM-scheduler roofline for this mixed read/write stream):
//   - 4 consecutive rows per block (same batch: 4 | 128), 128 threads
//   - one 8-float (256-bit) slot per thread (Blackwell v8 global ld/st)
//   - ALL 12 v8 loads front-batched (384B in flight/thread) before compute
//   - masked rows: streaming zero store only, no loads (skips ~40% of traffic)
//   - linear CTA order (swizzle -1.6us, persistent grid -3.4us,
//     store/load pipelining -1.5us: all measured slower)

#define BATCH 256
#define MAX_ATOM 128
#define N_FEAT 1024
#define THREADS 128        // N_FEAT / 8
#define ROWS_PER_BLK 4

struct f8 { float v[8]; };

__device__ __forceinline__ f8 ldnc8(const float* p) {
    f8 r;
    asm volatile("ld.global.nc.v8.f32 {%0,%1,%2,%3,%4,%5,%6,%7}, [%8];"
                 : "=f"(r.v[0]), "=f"(r.v[1]), "=f"(r.v[2]), "=f"(r.v[3]),
                   "=f"(r.v[4]), "=f"(r.v[5]), "=f"(r.v[6]), "=f"(r.v[7])
                 : "l"(p));
    return r;
}

__device__ __forceinline__ void stcs8(float* p, const f8& r) {
    asm volatile("st.global.cs.v8.f32 [%0], {%1,%2,%3,%4,%5,%6,%7,%8};"
                 :: "l"(p),
                    "f"(r.v[0]), "f"(r.v[1]), "f"(r.v[2]), "f"(r.v[3]),
                    "f"(r.v[4]), "f"(r.v[5]), "f"(r.v[6]), "f"(r.v[7])
                 : "memory");
}

__global__ __launch_bounds__(THREADS)
void dense_block_end_kernel(const float* __restrict__ features,
                            const float* __restrict__ residuals,
                            const void*  __restrict__ mol_slice,
                            float* __restrict__ out)
{
    const int row0 = blockIdx.x * ROWS_PER_BLK;
    const int b    = row0 >> 7;                  // / MAX_ATOM
    const int a0   = row0 & (MAX_ATOM - 1);

    // mol_slice dtype sniff:
    //   int32: [M0, 1024, M1, 1024, ...] -> word[1] == 1024
    //   int64: [M0, 0, 1024, 0, ...]     -> word[1] == 0 (hi word, M <= 128)
    const int* ms32 = (const int*)mol_slice;
    int n_atoms;
    if (ms32[1] == N_FEAT) {
        n_atoms = ms32[2 * b];
    } else {
        n_atoms = (int)((const long long*)mol_slice)[2 * b];
    }

    const size_t res_stride = (size_t)BATCH * MAX_ATOM * N_FEAT;
    const size_t base0 = (size_t)row0 * N_FEAT + threadIdx.x * 8;

    // Front-batch ALL loads (up to 12 independent 256-bit LDGs), then compute.
    f8 f[ROWS_PER_BLK], r0[ROWS_PER_BLK], r1[ROWS_PER_BLK];
    bool act[ROWS_PER_BLK];

    #pragma unroll
    for (int i = 0; i < ROWS_PER_BLK; i++) {
        act[i] = (a0 + i) < n_atoms;
        const size_t base = base0 + (size_t)i * N_FEAT;
        if (act[i]) {
            f[i]  = ldnc8(features + base);
            r0[i] = ldnc8(residuals + base);
            r1[i] = ldnc8(residuals + res_stride + base);
        }
    }

    #pragma unroll
    for (int i = 0; i < ROWS_PER_BLK; i++) {
        const size_t base = base0 + (size_t)i * N_FEAT;
        f8 v;
        #pragma unroll
        for (int j = 0; j < 8; j++) v.v[j] = 0.f;
        if (act[i]) {
            #pragma unroll
            for (int j = 0; j < 8; j++)
                v.v[j] = fmaxf(f[i].v[j] + r0[i].v[j] + r1[i].v[j], 0.f);
        }
        stcs8(out + base, v);
    }
}

extern "C" void kernel_launch(void* const* d_in, const int* in_sizes, int n_in,
                              void* d_out, int out_size)
{
    const float* features  = (const float*)d_in[0];
    const float* residuals = (const float*)d_in[1];
    const void*  mol_slice = d_in[2];
    float* out = (float*)d_out;

    dense_block_end_kernel<<<(BATCH * MAX_ATOM) / ROWS_PER_BLK, THREADS>>>(
        features, residuals, mol_slice, out);
}